// round 16
// baseline (speedup 1.0000x reference)
#include <cuda_runtime.h>
#include <cuda_fp16.h>
#include <cstdint>

// ---------------------------------------------------------------------------
// Problem constants
// ---------------------------------------------------------------------------
#define Bc   8
#define Nn   4096
#define Cc   384
#define Hh   8
#define HD   48
#define KDIM 384
#define M_ROWS (Bc*Nn)    // 32768
#define QKV_COLS (3*Cc)   // 1152
#define NBH  (Bc*Hh)      // 64
#define DN 0.3799178428257963f   // 48^-0.25
#define KEPS 1e-3f
#define EPS  1e-8f

// ---------------------------------------------------------------------------
// Scratch (device globals; allocation APIs are forbidden)
// ---------------------------------------------------------------------------
__device__ float g_kptv32[NBH*HD*HD];          // [bh][d][m]
__device__ float g_ks32  [NBH*HD];

__device__ __align__(128) __half g_xh  [M_ROWS*KDIM];       // x fp16
__device__ __align__(128) __half g_wq  [QKV_COLS*KDIM];
__device__ __align__(128) __half g_wp  [Cc*KDIM];
__device__ __align__(128) __half g_qph [NBH*Nn*HD];         // [bh][n][48]
__device__ __align__(128) __half g_kpTh[NBH*HD*Nn];         // [bh][m][n]
__device__ __align__(128) __half g_vTh [NBH*HD*Nn];         // [bh][d][n]
__device__ __align__(128) __half g_athi[M_ROWS*KDIM];       // attention out fp16
__device__ __align__(128) __half g_kvbh[NBH*64*HD];         // [bh][64][48] B for attn_out

// ---------------------------------------------------------------------------
// PTX helpers
// ---------------------------------------------------------------------------
__device__ __forceinline__ uint32_t smem_u32(const void* p) {
    uint32_t a;
    asm("{ .reg .u64 t; cvta.to.shared.u64 t, %1; cvt.u32.u64 %0, t; }" : "=r"(a) : "l"(p));
    return a;
}
__device__ __forceinline__ void cp16(uint32_t s, const void* g) {
    asm volatile("cp.async.cg.shared.global [%0], [%1], 16;" :: "r"(s), "l"(g) : "memory");
}
__device__ __forceinline__ void cp_commit() { asm volatile("cp.async.commit_group;" ::: "memory"); }
template <int N> __device__ __forceinline__ void cp_wait() {
    asm volatile("cp.async.wait_group %0;" :: "n"(N) : "memory");
}
#define LDSM4(r, a) \
    asm volatile("ldmatrix.sync.aligned.m8n8.x4.shared.b16 {%0,%1,%2,%3}, [%4];" \
        : "=r"((r)[0]), "=r"((r)[1]), "=r"((r)[2]), "=r"((r)[3]) : "r"(a))
#define LDSM2(r, a) \
    asm volatile("ldmatrix.sync.aligned.m8n8.x2.shared.b16 {%0,%1}, [%2];" \
        : "=r"((r)[0]), "=r"((r)[1]) : "r"(a))

__device__ __forceinline__ void mma16816(float* c, const uint32_t* a, const uint32_t* b) {
    asm volatile(
        "mma.sync.aligned.m16n8k16.row.col.f32.f16.f16.f32 "
        "{%0,%1,%2,%3}, {%4,%5,%6,%7}, {%8,%9}, {%0,%1,%2,%3};"
        : "+f"(c[0]), "+f"(c[1]), "+f"(c[2]), "+f"(c[3])
        : "r"(a[0]), "r"(a[1]), "r"(a[2]), "r"(a[3]), "r"(b[0]), "r"(b[1]));
}

// ---------------------------------------------------------------------------
// merged prep: x -> fp16, weights -> fp16, zero accumulators (one launch)
// ---------------------------------------------------------------------------
__global__ void prep_kernel(const float* __restrict__ x,
                            const float* __restrict__ Wqkv,
                            const float* __restrict__ Wproj) {
    int i = blockIdx.x * 256 + threadIdx.x;
    if (i < M_ROWS*KDIM/4) {
        float4 v = ((const float4*)x)[i];
        ((__half2*)g_xh)[i*2]   = __half2(__float2half(v.x), __float2half(v.y));
        ((__half2*)g_xh)[i*2+1] = __half2(__float2half(v.z), __float2half(v.w));
    }
    if (i < QKV_COLS*KDIM/4) {
        float4 v = ((const float4*)Wqkv)[i];
        ((__half2*)g_wq)[i*2]   = __half2(__float2half(v.x), __float2half(v.y));
        ((__half2*)g_wq)[i*2+1] = __half2(__float2half(v.z), __float2half(v.w));
    }
    if (i < Cc*KDIM/4) {
        float4 v = ((const float4*)Wproj)[i];
        ((__half2*)g_wp)[i*2]   = __half2(__float2half(v.x), __float2half(v.y));
        ((__half2*)g_wp)[i*2+1] = __half2(__float2half(v.z), __float2half(v.w));
    }
    if (i < NBH*HD*HD/4) ((float4*)g_kptv32)[i] = make_float4(0.f, 0.f, 0.f, 0.f);
    if (i < NBH*HD/4)    ((float4*)g_ks32)[i]   = make_float4(0.f, 0.f, 0.f, 0.f);
}

// ---------------------------------------------------------------------------
// Single-fp16 tensor-core GEMM via mma.sync. C = A(M_ROWS x 384) @ W^T
// CTA tile 128 x 192; 256 threads (8 warps, warp tile 64x48).
// K chunks of 32, FOUR stages, single __syncthreads per iteration.
// ybase shifts the column-block index (lets GEMM1 be split into q / kv parts).
// MODE 0: QKV feature-map epilogue (qp; kpT/vT transposed)
// MODE 1: out = acc + bias (fp32)
// ---------------------------------------------------------------------------
#define KC 32
#define A_ROW_B 80            // 40 halfs
#define OFF_W   10240         // 128*80
#define STG     25600         // 10240 + 192*80 ; 4 stages = 102400
#define NCH     (KDIM/KC)     // 12
#define SMEM_TOTAL 102912     // epilogue buffer 128*201*4 dominates

template <int MODE>
__global__ __launch_bounds__(256) void gemm_mma(
    const __half* __restrict__ A, const __half* __restrict__ W, int ybase,
    const float* __restrict__ bias, float* __restrict__ out)
{
    extern __shared__ char smem[];
    const uint32_t sb = smem_u32(smem);
    const int tid = threadIdx.x;
    const int wid = tid >> 5;
    const int l   = tid & 31;
    const int wm  = wid & 1;
    const int wn  = wid >> 1;
    const int yb   = blockIdx.y + ybase;
    const int row0 = blockIdx.x * 128;
    const int col0 = yb * 192;

    auto load_chunk = [&](int L, int s) {
        const uint32_t st = sb + s * STG;
        const int kof = L * KC;
        #pragma unroll
        for (int i = 0; i < 2; i++) {            // A: 128 rows x 4 segs
            int idx = tid + i * 256;
            int row = idx >> 2, seg = idx & 3;
            cp16(st + (uint32_t)(row * A_ROW_B + seg * 16),
                 A + (size_t)(row0 + row) * KDIM + kof + seg * 8);
        }
        #pragma unroll
        for (int i = 0; i < 3; i++) {            // W: 192 rows x 4 segs
            int idx = tid + i * 256;
            int row = idx >> 2, seg = idx & 3;
            cp16(st + OFF_W + (uint32_t)(row * A_ROW_B + seg * 16),
                 W + (size_t)(col0 + row) * KDIM + kof + seg * 8);
        }
        cp_commit();
    };

    const uint32_t a_base = (uint32_t)(((wm*64 + (l & 15)) * 40 + (l >> 4) * 8) * 2);
    const uint32_t b_base = (uint32_t)(((wn*48 + ((l >> 4) & 1) * 8 + (l & 7)) * 40
                                        + ((l >> 3) & 1) * 8) * 2);

    float acc[4][6][4];
    #pragma unroll
    for (int mt = 0; mt < 4; mt++)
        #pragma unroll
        for (int nt = 0; nt < 6; nt++)
            #pragma unroll
            for (int r = 0; r < 4; r++) acc[mt][nt][r] = 0.f;

    load_chunk(0, 0);
    load_chunk(1, 1);
    load_chunk(2, 2);

    #pragma unroll 1
    for (int c = 0; c < NCH; c++) {
        if (c < NCH - 2)      cp_wait<2>();
        else if (c == NCH-2)  cp_wait<1>();
        else                  cp_wait<0>();
        __syncthreads();
        if (c + 3 < NCH) load_chunk(c + 3, (c + 3) & 3);

        const uint32_t st = sb + (c & 3) * STG;
        #pragma unroll
        for (int ks = 0; ks < 2; ks++) {
            const uint32_t ko = ks * 32;
            uint32_t ah[4][4], bh[3][4];
            #pragma unroll
            for (int np = 0; np < 3; np++)
                LDSM4(bh[np], st + OFF_W + b_base + np*1280 + ko);
            #pragma unroll
            for (int mt = 0; mt < 4; mt++)
                LDSM4(ah[mt], st + a_base + mt*1280 + ko);
            #pragma unroll
            for (int mt = 0; mt < 4; mt++)
                #pragma unroll
                for (int np = 0; np < 3; np++)
                    #pragma unroll
                    for (int hf = 0; hf < 2; hf++)
                        mma16816(acc[mt][np*2 + hf], ah[mt], &bh[np][hf*2]);
        }
    }
    __syncthreads();   // all compute done before epilogue reuses smem

    // ---- epilogue via smem [128][201] fp32 (odd pad; scalar stores) ----
    float* epi = (float*)smem;
    const int g   = l >> 2;
    const int tig = l & 3;
    #pragma unroll
    for (int mt = 0; mt < 4; mt++)
        #pragma unroll
        for (int nt = 0; nt < 6; nt++) {
            int row = wm*64 + mt*16 + g;
            int col = wn*48 + nt*8 + 2*tig;
            epi[row * 201 + col]           = acc[mt][nt][0];
            epi[row * 201 + col + 1]       = acc[mt][nt][1];
            epi[(row + 8) * 201 + col]     = acc[mt][nt][2];
            epi[(row + 8) * 201 + col + 1] = acc[mt][nt][3];
        }
    __syncthreads();

    if (MODE == 0) {
        const int b  = row0 >> 12;
        const int n0 = row0 & (Nn - 1);
        #pragma unroll
        for (int g4 = 0; g4 < 4; g4++) {
            const int gg = yb * 4 + g4;
            const int sI = gg >> 3;        // 0=q,1=k,2=v
            const int h  = gg & 7;
            const int bh = b * Hh + h;
            if (sI == 0) {
                const size_t base = ((size_t)bh * Nn + n0) * HD;
                #pragma unroll 4
                for (int it = 0; it < 24; it++) {
                    int idx = tid + it * 256;
                    int m = idx / 48, e = idx - m * 48;
                    float v = epi[m * 201 + g4 * 48 + e];
                    v = fmaxf(v * DN, 0.f) + KEPS;
                    g_qph[base + idx] = __float2half(v);
                }
            } else {
                __half* Ph = (sI == 1) ? g_kpTh : g_vTh;
                const size_t base = (size_t)bh * HD * Nn;
                #pragma unroll 4
                for (int it = 0; it < 24; it++) {
                    int idx = tid + it * 256;
                    int e = idx >> 7, m = idx & 127;
                    float v = epi[m * 201 + g4 * 48 + e];
                    if (sI == 1) v = fmaxf(v * DN, 0.f) + KEPS;
                    Ph[base + (size_t)e * Nn + n0 + m] = __float2half(v);
                }
            }
        }
    } else {
        #pragma unroll 8
        for (int it = 0; it < 96; it++) {
            int idx = tid + it * 256;
            int m = idx / 192, j = idx - m * 192;
            out[(size_t)(row0 + m) * Cc + col0 + j] = epi[m * 201 + j] + bias[col0 + j];
        }
    }
}

// ---------------------------------------------------------------------------
// kv_agg on tensor cores (single fp16): per (bh, split):
// C[64 x 48] += Arows @ kpT^T over n; A rows 0-47 = vT, row 48 = ones (-> ks).
// K chunks of 64 n, 3-stage cp.async, split-K 8.
// ---------------------------------------------------------------------------
#define KC2 64
#define SPLITK 8
#define NCH2 ((Nn/SPLITK)/KC2)   // 8
#define AROWB2 144               // 72 halfs
#define OFF2_B 9216              // 64*144
#define STG2   16128             // 9216 + 48*144
#define SMEM2  (3*STG2)          // 48384

__global__ __launch_bounds__(256) void kv_agg_mma()
{
    extern __shared__ char smem[];
    const uint32_t sb = smem_u32(smem);
    const int tid = threadIdx.x;
    const int wid = tid >> 5;
    const int l   = tid & 31;
    const int bh  = blockIdx.x;
    const int n_base = blockIdx.y * (Nn / SPLITK);

    // preset constant A rows 48-63 in all 3 stages (row 48 = 1, rest 0)
    for (int i = tid; i < 3 * 16 * 64; i += 256) {
        int s = i / 1024, rr = (i >> 6) & 15, cc = i & 63;
        *(__half*)(smem + s*STG2 + (48 + rr)*AROWB2 + cc*2) =
            (rr == 0) ? __float2half(1.f) : __float2half(0.f);
    }
    __syncthreads();

    const __half* vT  = g_vTh  + (size_t)bh*HD*Nn;
    const __half* kpT = g_kpTh + (size_t)bh*HD*Nn;

    auto load_chunk = [&](int ch, int s) {
        const uint32_t st = sb + s * STG2;
        const int n0 = n_base + ch * KC2;
        #pragma unroll
        for (int i = 0; i < 3; i++) {
            int idx = tid + i * 256;          // 0..767
            int arr = idx / 384;              // 0 = vT, 1 = kpT
            int rem = idx - arr * 384;
            int row = rem >> 3, seg = rem & 7;
            cp16(st + (arr ? OFF2_B : 0) + (uint32_t)(row * AROWB2 + seg * 16),
                 (arr ? kpT : vT) + (size_t)row * Nn + n0 + seg * 8);
        }
        cp_commit();
    };

    const int wm = wid & 3;       // 4 M-tiles of 16
    const int wn = wid >> 2;      // 2 N-halves of 24
    const uint32_t a_base  = (uint32_t)((wm*16 + (l & 15)) * AROWB2 + (l >> 4) * 16);
    const uint32_t b16     = (uint32_t)((wn*24 + ((l >> 4) & 1)*8 + (l & 7)) * AROWB2
                                        + ((l >> 3) & 1) * 16);
    const uint32_t b8      = (uint32_t)((wn*24 + 16 + (l & 7)) * AROWB2
                                        + ((l >> 3) & 1) * 16);

    float acc[3][4];
    #pragma unroll
    for (int nt = 0; nt < 3; nt++)
        #pragma unroll
        for (int r = 0; r < 4; r++) acc[nt][r] = 0.f;

    load_chunk(0, 0);
    load_chunk(1, 1);
    load_chunk(2, 2);

    #pragma unroll 1
    for (int c = 0; c < NCH2; c++) {
        if (c < NCH2 - 2)      cp_wait<2>();
        else if (c == NCH2-2)  cp_wait<1>();
        else                   cp_wait<0>();
        __syncthreads();
        const uint32_t st = sb + (c % 3) * STG2;

        #pragma unroll
        for (int ks = 0; ks < 4; ks++) {
            const uint32_t ko = ks * 32;
            uint32_t ah[4], bh01[4], bh2[2];
            LDSM4(ah,   st + a_base + ko);
            LDSM4(bh01, st + OFF2_B + b16 + ko);
            LDSM2(bh2,  st + OFF2_B + b8 + ko);
            mma16816(acc[0], ah, &bh01[0]);
            mma16816(acc[1], ah, &bh01[2]);
            mma16816(acc[2], ah, bh2);
        }
        __syncthreads();
        if (c + 3 < NCH2) load_chunk(c + 3, c % 3);
    }

    // epilogue: atomic reduce. C row = d (or 48 -> ks), col = m.
    const int rowg = wm*16 + (l >> 2);
    #pragma unroll
    for (int nt = 0; nt < 3; nt++) {
        int col = wn*24 + nt*8 + (l & 3)*2;
        #pragma unroll
        for (int rr = 0; rr < 2; rr++) {
            int d = rowg + rr*8;
            if (d < HD) {
                atomicAdd(&g_kptv32[((size_t)bh*HD + d)*HD + col],     acc[nt][rr*2]);
                atomicAdd(&g_kptv32[((size_t)bh*HD + d)*HD + col + 1], acc[nt][rr*2+1]);
            } else if (d == HD) {
                atomicAdd(&g_ks32[bh*HD + col],     acc[nt][rr*2]);
                atomicAdd(&g_ks32[bh*HD + col + 1], acc[nt][rr*2+1]);
            }
        }
    }
}

// ---------------------------------------------------------------------------
// convert kptv/ks -> fp16 B matrix [bh][64][48]; vectorized float4, grid 192.
// ---------------------------------------------------------------------------
__global__ void kvb_conv_kernel()
{
    int i = blockIdx.x * 256 + threadIdx.x;          // 0 .. 64*64*12-1
    if (i >= NBH * 64 * 12) return;
    int bh  = i / 768;
    int rem = i - bh * 768;
    int row = rem / 12;
    int c4  = (rem - row * 12) * 4;

    float4 v;
    if (row < HD)       v = *(const float4*)&g_kptv32[((size_t)bh*HD + row)*HD + c4];
    else if (row == HD) v = *(const float4*)&g_ks32[bh*HD + c4];
    else                v = make_float4(0.f, 0.f, 0.f, 0.f);

    __half2* dst = (__half2*)&g_kvbh[(size_t)bh*64*HD + row*HD + c4];
    dst[0] = __half2(__float2half(v.x), __float2half(v.y));
    dst[1] = __half2(__float2half(v.z), __float2half(v.w));
}

// ---------------------------------------------------------------------------
// attn_out on tensor cores (single fp16): per (bh, 128-token block):
// C[128 x 64] = qp(128x48) @ Bt(64x48)^T ; col 48 = D; att = C[:, :48]/(D+eps)
// ---------------------------------------------------------------------------
#define AO_ROWB 112          // 56 halfs
#define AO_B  14336          // 128*112
#define AO_SMEM 21504        // + 64*112

__global__ __launch_bounds__(256) void attn_out_mma()
{
    extern __shared__ char smem[];
    const uint32_t sb = smem_u32(smem);
    const int tid = threadIdx.x;
    const int wid = tid >> 5;
    const int l   = tid & 31;
    const int bh  = blockIdx.x;
    const int n0  = blockIdx.y * 128;

    // load A (qp): 128 rows x 6 segs = 768 over 256 thr
    #pragma unroll
    for (int i = 0; i < 3; i++) {
        int idx = tid + i * 256;
        int row = idx / 6, seg = idx - row * 6;
        cp16(sb + (uint32_t)(row * AO_ROWB + seg * 16),
             g_qph + ((size_t)bh * Nn + n0 + row) * HD + seg * 8);
    }
    // load B (kvb): 64 rows x 6 segs = 384
    #pragma unroll
    for (int i = 0; i < 2; i++) {
        int idx = tid + i * 256;
        if (idx < 384) {
            int row = idx / 6, seg = idx - row * 6;
            cp16(sb + AO_B + (uint32_t)(row * AO_ROWB + seg * 16),
                 g_kvbh + bh*64*HD + row * HD + seg * 8);
        }
    }
    cp_commit();
    cp_wait<0>();
    __syncthreads();

    float acc[7][4];
    #pragma unroll
    for (int nt = 0; nt < 7; nt++)
        #pragma unroll
        for (int r = 0; r < 4; r++) acc[nt][r] = 0.f;

    // 8 warps x 16 rows = 128
    const uint32_t a_base = (uint32_t)((wid*16 + (l & 15)) * AO_ROWB + (l >> 4) * 16);
    const uint32_t b_base = (uint32_t)((((l >> 4) & 1)*8 + (l & 7)) * AO_ROWB
                                       + ((l >> 3) & 1) * 16);

    #pragma unroll
    for (int k = 0; k < 3; k++) {
        const uint32_t ko = k * 32;
        uint32_t bhf[4][4];
        #pragma unroll
        for (int bt = 0; bt < 4; bt++)
            LDSM4(bhf[bt], sb + AO_B + b_base + bt*16*AO_ROWB + ko);
        uint32_t ah[4];
        LDSM4(ah, sb + a_base + ko);
        #pragma unroll
        for (int nt = 0; nt < 7; nt++)    // nt 6 = D column (48..55)
            mma16816(acc[nt], ah, &bhf[nt >> 1][(nt & 1)*2]);
    }

    // epilogue: D = col 48 (tile 6 col 0, lanes l&3==0); divide, store fp16
    float D0 = __shfl_sync(0xFFFFFFFFu, acc[6][0], l & 0x1C);
    float D1 = __shfl_sync(0xFFFFFFFFu, acc[6][2], l & 0x1C);
    float inv0 = 1.f / (D0 + EPS);
    float inv1 = 1.f / (D1 + EPS);
    int r0 = wid*16 + (l >> 2);
    size_t rowbase0 = ((size_t)bh * Nn + n0 + r0) * HD;
    size_t rowbase1 = ((size_t)bh * Nn + n0 + r0 + 8) * HD;
    #pragma unroll
    for (int nt = 0; nt < 6; nt++) {
        int col = nt*8 + (l & 3)*2;
        __half2 h0 = __half2(__float2half(acc[nt][0]*inv0),
                             __float2half(acc[nt][1]*inv0));
        __half2 h1 = __half2(__float2half(acc[nt][2]*inv1),
                             __float2half(acc[nt][3]*inv1));
        *(__half2*)&g_athi[rowbase0 + col] = h0;
        *(__half2*)&g_athi[rowbase1 + col] = h1;
    }
}

// ---------------------------------------------------------------------------
extern "C" void kernel_launch(void* const* d_in, const int* in_sizes, int n_in,
                              void* d_out, int out_size)
{
    (void)in_sizes; (void)n_in; (void)out_size;
    const float* x     = (const float*)d_in[0];
    const float* Wqkv  = (const float*)d_in[1];
    const float* Wproj = (const float*)d_in[2];
    const float* bproj = (const float*)d_in[3];
    float* out = (float*)d_out;

    // one-time host-side resources (no device memory; identical work per call)
    static cudaStream_t s2 = nullptr;
    static cudaEvent_t evA = nullptr, evB = nullptr;
    if (s2 == nullptr) {
        cudaStreamCreateWithFlags(&s2, cudaStreamNonBlocking);
        cudaEventCreateWithFlags(&evA, cudaEventDisableTiming);
        cudaEventCreateWithFlags(&evB, cudaEventDisableTiming);
    }

    cudaFuncSetAttribute(gemm_mma<0>, cudaFuncAttributeMaxDynamicSharedMemorySize, SMEM_TOTAL);
    cudaFuncSetAttribute(gemm_mma<1>, cudaFuncAttributeMaxDynamicSharedMemorySize, SMEM_TOTAL);
    cudaFuncSetAttribute(kv_agg_mma,   cudaFuncAttributeMaxDynamicSharedMemorySize, SMEM2);
    cudaFuncSetAttribute(attn_out_mma, cudaFuncAttributeMaxDynamicSharedMemorySize, AO_SMEM);

    __half *xh, *wq, *wp, *athi;
    cudaGetSymbolAddress((void**)&xh,   g_xh);
    cudaGetSymbolAddress((void**)&wq,   g_wq);
    cudaGetSymbolAddress((void**)&wp,   g_wp);
    cudaGetSymbolAddress((void**)&athi, g_athi);

    prep_kernel<<<(M_ROWS*KDIM/4 + 255)/256, 256>>>(x, Wqkv, Wproj);

    // fork: q-column GEMM1 on s2, kv-column GEMM1 + kv_agg + kvb on default
    cudaEventRecord(evA, 0);
    cudaStreamWaitEvent(s2, evA, 0);
    gemm_mma<0><<<dim3(M_ROWS/128, 2), 256, SMEM_TOTAL, s2>>>(
        xh, wq, 0, nullptr, nullptr);                     // y 0-1 (q)
    cudaEventRecord(evB, s2);

    gemm_mma<0><<<dim3(M_ROWS/128, 4), 256, SMEM_TOTAL>>>(
        xh, wq, 2, nullptr, nullptr);                     // y 2-5 (k, v)
    kv_agg_mma<<<dim3(NBH, SPLITK), 256, SMEM2>>>();
    kvb_conv_kernel<<<(NBH*64*12 + 255)/256, 256>>>();

    // join: attn_out needs qp (s2) and kvb (default)
    cudaStreamWaitEvent(0, evB, 0);
    attn_out_mma<<<dim3(NBH, Nn/128), 256, AO_SMEM>>>();

    gemm_mma<1><<<dim3(M_ROWS/128, Cc/192), 256, SMEM_TOTAL>>>(
        athi, wp, 0, bproj, out);
}

// round 17
// speedup vs baseline: 1.0193x; 1.0193x over previous
#include <cuda_runtime.h>
#include <cuda_fp16.h>
#include <cstdint>

// ---------------------------------------------------------------------------
// Problem constants
// ---------------------------------------------------------------------------
#define Bc   8
#define Nn   4096
#define Cc   384
#define Hh   8
#define HD   48
#define KDIM 384
#define M_ROWS (Bc*Nn)    // 32768
#define QKV_COLS (3*Cc)   // 1152
#define NBH  (Bc*Hh)      // 64
#define DN 0.3799178428257963f   // 48^-0.25
#define KEPS 1e-3f
#define EPS  1e-8f

// ---------------------------------------------------------------------------
// Scratch (device globals; allocation APIs are forbidden)
// ---------------------------------------------------------------------------
__device__ float g_kptv32[NBH*HD*HD];          // [bh][d][m]
__device__ float g_ks32  [NBH*HD];

__device__ __align__(128) __half g_xh  [M_ROWS*KDIM];       // x fp16
__device__ __align__(128) __half g_wq  [QKV_COLS*KDIM];
__device__ __align__(128) __half g_wp  [Cc*KDIM];
__device__ __align__(128) __half g_qph [NBH*Nn*HD];         // [bh][n][48]
__device__ __align__(128) __half g_kpTh[NBH*HD*Nn];         // [bh][m][n]
__device__ __align__(128) __half g_vTh [NBH*HD*Nn];         // [bh][d][n]
__device__ __align__(128) __half g_athi[M_ROWS*KDIM];       // attention out fp16
__device__ __align__(128) __half g_kvbh[NBH*64*HD];         // [bh][64][48] B for attn_out

// ---------------------------------------------------------------------------
// PTX helpers
// ---------------------------------------------------------------------------
__device__ __forceinline__ uint32_t smem_u32(const void* p) {
    uint32_t a;
    asm("{ .reg .u64 t; cvta.to.shared.u64 t, %1; cvt.u32.u64 %0, t; }" : "=r"(a) : "l"(p));
    return a;
}
__device__ __forceinline__ void cp16(uint32_t s, const void* g) {
    asm volatile("cp.async.cg.shared.global [%0], [%1], 16;" :: "r"(s), "l"(g) : "memory");
}
__device__ __forceinline__ void cp_commit() { asm volatile("cp.async.commit_group;" ::: "memory"); }
template <int N> __device__ __forceinline__ void cp_wait() {
    asm volatile("cp.async.wait_group %0;" :: "n"(N) : "memory");
}
#define LDSM4(r, a) \
    asm volatile("ldmatrix.sync.aligned.m8n8.x4.shared.b16 {%0,%1,%2,%3}, [%4];" \
        : "=r"((r)[0]), "=r"((r)[1]), "=r"((r)[2]), "=r"((r)[3]) : "r"(a))
#define LDSM2(r, a) \
    asm volatile("ldmatrix.sync.aligned.m8n8.x2.shared.b16 {%0,%1}, [%2];" \
        : "=r"((r)[0]), "=r"((r)[1]) : "r"(a))

__device__ __forceinline__ void mma16816(float* c, const uint32_t* a, const uint32_t* b) {
    asm volatile(
        "mma.sync.aligned.m16n8k16.row.col.f32.f16.f16.f32 "
        "{%0,%1,%2,%3}, {%4,%5,%6,%7}, {%8,%9}, {%0,%1,%2,%3};"
        : "+f"(c[0]), "+f"(c[1]), "+f"(c[2]), "+f"(c[3])
        : "r"(a[0]), "r"(a[1]), "r"(a[2]), "r"(a[3]), "r"(b[0]), "r"(b[1]));
}

// ---------------------------------------------------------------------------
// merged prep: x -> fp16, weights -> fp16, zero accumulators (one launch)
// ---------------------------------------------------------------------------
__global__ void prep_kernel(const float* __restrict__ x,
                            const float* __restrict__ Wqkv,
                            const float* __restrict__ Wproj) {
    int i = blockIdx.x * 256 + threadIdx.x;
    if (i < M_ROWS*KDIM/4) {
        float4 v = ((const float4*)x)[i];
        ((__half2*)g_xh)[i*2]   = __half2(__float2half(v.x), __float2half(v.y));
        ((__half2*)g_xh)[i*2+1] = __half2(__float2half(v.z), __float2half(v.w));
    }
    if (i < QKV_COLS*KDIM/4) {
        float4 v = ((const float4*)Wqkv)[i];
        ((__half2*)g_wq)[i*2]   = __half2(__float2half(v.x), __float2half(v.y));
        ((__half2*)g_wq)[i*2+1] = __half2(__float2half(v.z), __float2half(v.w));
    }
    if (i < Cc*KDIM/4) {
        float4 v = ((const float4*)Wproj)[i];
        ((__half2*)g_wp)[i*2]   = __half2(__float2half(v.x), __float2half(v.y));
        ((__half2*)g_wp)[i*2+1] = __half2(__float2half(v.z), __float2half(v.w));
    }
    if (i < NBH*HD*HD/4) ((float4*)g_kptv32)[i] = make_float4(0.f, 0.f, 0.f, 0.f);
    if (i < NBH*HD/4)    ((float4*)g_ks32)[i]   = make_float4(0.f, 0.f, 0.f, 0.f);
}

// ---------------------------------------------------------------------------
// Single-fp16 tensor-core GEMM via mma.sync. C = A(M_ROWS x 384) @ W^T
// CTA tile 128 x 192; 256 threads (8 warps, warp tile 64x48).
// K chunks of 32, FOUR stages, single __syncthreads per iteration.
// ybase shifts the column-block index (GEMM1 split into kv / q parts).
// MODE 0: QKV feature-map epilogue (qp; kpT/vT transposed)
// MODE 1: out = acc + bias (fp32)
// ---------------------------------------------------------------------------
#define KC 32
#define A_ROW_B 80            // 40 halfs
#define OFF_W   10240         // 128*80
#define STG     25600         // 10240 + 192*80 ; 4 stages = 102400
#define NCH     (KDIM/KC)     // 12
#define SMEM_TOTAL 102912     // epilogue buffer 128*201*4 dominates

template <int MODE>
__global__ __launch_bounds__(256) void gemm_mma(
    const __half* __restrict__ A, const __half* __restrict__ W, int ybase,
    const float* __restrict__ bias, float* __restrict__ out)
{
    extern __shared__ char smem[];
    const uint32_t sb = smem_u32(smem);
    const int tid = threadIdx.x;
    const int wid = tid >> 5;
    const int l   = tid & 31;
    const int wm  = wid & 1;
    const int wn  = wid >> 1;
    const int yb   = blockIdx.y + ybase;
    const int row0 = blockIdx.x * 128;
    const int col0 = yb * 192;

    auto load_chunk = [&](int L, int s) {
        const uint32_t st = sb + s * STG;
        const int kof = L * KC;
        #pragma unroll
        for (int i = 0; i < 2; i++) {            // A: 128 rows x 4 segs
            int idx = tid + i * 256;
            int row = idx >> 2, seg = idx & 3;
            cp16(st + (uint32_t)(row * A_ROW_B + seg * 16),
                 A + (size_t)(row0 + row) * KDIM + kof + seg * 8);
        }
        #pragma unroll
        for (int i = 0; i < 3; i++) {            // W: 192 rows x 4 segs
            int idx = tid + i * 256;
            int row = idx >> 2, seg = idx & 3;
            cp16(st + OFF_W + (uint32_t)(row * A_ROW_B + seg * 16),
                 W + (size_t)(col0 + row) * KDIM + kof + seg * 8);
        }
        cp_commit();
    };

    const uint32_t a_base = (uint32_t)(((wm*64 + (l & 15)) * 40 + (l >> 4) * 8) * 2);
    const uint32_t b_base = (uint32_t)(((wn*48 + ((l >> 4) & 1) * 8 + (l & 7)) * 40
                                        + ((l >> 3) & 1) * 8) * 2);

    float acc[4][6][4];
    #pragma unroll
    for (int mt = 0; mt < 4; mt++)
        #pragma unroll
        for (int nt = 0; nt < 6; nt++)
            #pragma unroll
            for (int r = 0; r < 4; r++) acc[mt][nt][r] = 0.f;

    load_chunk(0, 0);
    load_chunk(1, 1);
    load_chunk(2, 2);

    #pragma unroll 1
    for (int c = 0; c < NCH; c++) {
        if (c < NCH - 2)      cp_wait<2>();
        else if (c == NCH-2)  cp_wait<1>();
        else                  cp_wait<0>();
        __syncthreads();
        if (c + 3 < NCH) load_chunk(c + 3, (c + 3) & 3);

        const uint32_t st = sb + (c & 3) * STG;
        #pragma unroll
        for (int ks = 0; ks < 2; ks++) {
            const uint32_t ko = ks * 32;
            uint32_t ah[4][4], bh[3][4];
            #pragma unroll
            for (int np = 0; np < 3; np++)
                LDSM4(bh[np], st + OFF_W + b_base + np*1280 + ko);
            #pragma unroll
            for (int mt = 0; mt < 4; mt++)
                LDSM4(ah[mt], st + a_base + mt*1280 + ko);
            #pragma unroll
            for (int mt = 0; mt < 4; mt++)
                #pragma unroll
                for (int np = 0; np < 3; np++)
                    #pragma unroll
                    for (int hf = 0; hf < 2; hf++)
                        mma16816(acc[mt][np*2 + hf], ah[mt], &bh[np][hf*2]);
        }
    }
    __syncthreads();   // all compute done before epilogue reuses smem

    // ---- epilogue via smem [128][201] fp32 (odd pad; scalar stores) ----
    float* epi = (float*)smem;
    const int g   = l >> 2;
    const int tig = l & 3;
    #pragma unroll
    for (int mt = 0; mt < 4; mt++)
        #pragma unroll
        for (int nt = 0; nt < 6; nt++) {
            int row = wm*64 + mt*16 + g;
            int col = wn*48 + nt*8 + 2*tig;
            epi[row * 201 + col]           = acc[mt][nt][0];
            epi[row * 201 + col + 1]       = acc[mt][nt][1];
            epi[(row + 8) * 201 + col]     = acc[mt][nt][2];
            epi[(row + 8) * 201 + col + 1] = acc[mt][nt][3];
        }
    __syncthreads();

    if (MODE == 0) {
        const int b  = row0 >> 12;
        const int n0 = row0 & (Nn - 1);
        #pragma unroll
        for (int g4 = 0; g4 < 4; g4++) {
            const int gg = yb * 4 + g4;
            const int sI = gg >> 3;        // 0=q,1=k,2=v
            const int h  = gg & 7;
            const int bh = b * Hh + h;
            if (sI == 0) {
                const size_t base = ((size_t)bh * Nn + n0) * HD;
                #pragma unroll 4
                for (int it = 0; it < 24; it++) {
                    int idx = tid + it * 256;
                    int m = idx / 48, e = idx - m * 48;
                    float v = epi[m * 201 + g4 * 48 + e];
                    v = fmaxf(v * DN, 0.f) + KEPS;
                    g_qph[base + idx] = __float2half(v);
                }
            } else {
                __half* Ph = (sI == 1) ? g_kpTh : g_vTh;
                const size_t base = (size_t)bh * HD * Nn;
                #pragma unroll 4
                for (int it = 0; it < 24; it++) {
                    int idx = tid + it * 256;
                    int e = idx >> 7, m = idx & 127;
                    float v = epi[m * 201 + g4 * 48 + e];
                    if (sI == 1) v = fmaxf(v * DN, 0.f) + KEPS;
                    Ph[base + (size_t)e * Nn + n0 + m] = __float2half(v);
                }
            }
        }
    } else {
        #pragma unroll 8
        for (int it = 0; it < 96; it++) {
            int idx = tid + it * 256;
            int m = idx / 192, j = idx - m * 192;
            out[(size_t)(row0 + m) * Cc + col0 + j] = epi[m * 201 + j] + bias[col0 + j];
        }
    }
}

// ---------------------------------------------------------------------------
// kv_agg on tensor cores (single fp16): per (bh, split):
// C[64 x 48] += Arows @ kpT^T over n; A rows 0-47 = vT, row 48 = ones (-> ks).
// K chunks of 64 n, 3-stage cp.async, split-K 8.
// ---------------------------------------------------------------------------
#define KC2 64
#define SPLITK 8
#define NCH2 ((Nn/SPLITK)/KC2)   // 8
#define AROWB2 144               // 72 halfs
#define OFF2_B 9216              // 64*144
#define STG2   16128             // 9216 + 48*144
#define SMEM2  (3*STG2)          // 48384

__global__ __launch_bounds__(256) void kv_agg_mma()
{
    extern __shared__ char smem[];
    const uint32_t sb = smem_u32(smem);
    const int tid = threadIdx.x;
    const int wid = tid >> 5;
    const int l   = tid & 31;
    const int bh  = blockIdx.x;
    const int n_base = blockIdx.y * (Nn / SPLITK);

    // preset constant A rows 48-63 in all 3 stages (row 48 = 1, rest 0)
    for (int i = tid; i < 3 * 16 * 64; i += 256) {
        int s = i / 1024, rr = (i >> 6) & 15, cc = i & 63;
        *(__half*)(smem + s*STG2 + (48 + rr)*AROWB2 + cc*2) =
            (rr == 0) ? __float2half(1.f) : __float2half(0.f);
    }
    __syncthreads();

    const __half* vT  = g_vTh  + (size_t)bh*HD*Nn;
    const __half* kpT = g_kpTh + (size_t)bh*HD*Nn;

    auto load_chunk = [&](int ch, int s) {
        const uint32_t st = sb + s * STG2;
        const int n0 = n_base + ch * KC2;
        #pragma unroll
        for (int i = 0; i < 3; i++) {
            int idx = tid + i * 256;          // 0..767
            int arr = idx / 384;              // 0 = vT, 1 = kpT
            int rem = idx - arr * 384;
            int row = rem >> 3, seg = rem & 7;
            cp16(st + (arr ? OFF2_B : 0) + (uint32_t)(row * AROWB2 + seg * 16),
                 (arr ? kpT : vT) + (size_t)row * Nn + n0 + seg * 8);
        }
        cp_commit();
    };

    const int wm = wid & 3;       // 4 M-tiles of 16
    const int wn = wid >> 2;      // 2 N-halves of 24
    const uint32_t a_base  = (uint32_t)((wm*16 + (l & 15)) * AROWB2 + (l >> 4) * 16);
    const uint32_t b16     = (uint32_t)((wn*24 + ((l >> 4) & 1)*8 + (l & 7)) * AROWB2
                                        + ((l >> 3) & 1) * 16);
    const uint32_t b8      = (uint32_t)((wn*24 + 16 + (l & 7)) * AROWB2
                                        + ((l >> 3) & 1) * 16);

    float acc[3][4];
    #pragma unroll
    for (int nt = 0; nt < 3; nt++)
        #pragma unroll
        for (int r = 0; r < 4; r++) acc[nt][r] = 0.f;

    load_chunk(0, 0);
    load_chunk(1, 1);
    load_chunk(2, 2);

    #pragma unroll 1
    for (int c = 0; c < NCH2; c++) {
        if (c < NCH2 - 2)      cp_wait<2>();
        else if (c == NCH2-2)  cp_wait<1>();
        else                   cp_wait<0>();
        __syncthreads();
        const uint32_t st = sb + (c % 3) * STG2;

        #pragma unroll
        for (int ks = 0; ks < 4; ks++) {
            const uint32_t ko = ks * 32;
            uint32_t ah[4], bh01[4], bh2[2];
            LDSM4(ah,   st + a_base + ko);
            LDSM4(bh01, st + OFF2_B + b16 + ko);
            LDSM2(bh2,  st + OFF2_B + b8 + ko);
            mma16816(acc[0], ah, &bh01[0]);
            mma16816(acc[1], ah, &bh01[2]);
            mma16816(acc[2], ah, bh2);
        }
        __syncthreads();
        if (c + 3 < NCH2) load_chunk(c + 3, c % 3);
    }

    // epilogue: atomic reduce. C row = d (or 48 -> ks), col = m.
    const int rowg = wm*16 + (l >> 2);
    #pragma unroll
    for (int nt = 0; nt < 3; nt++) {
        int col = wn*24 + nt*8 + (l & 3)*2;
        #pragma unroll
        for (int rr = 0; rr < 2; rr++) {
            int d = rowg + rr*8;
            if (d < HD) {
                atomicAdd(&g_kptv32[((size_t)bh*HD + d)*HD + col],     acc[nt][rr*2]);
                atomicAdd(&g_kptv32[((size_t)bh*HD + d)*HD + col + 1], acc[nt][rr*2+1]);
            } else if (d == HD) {
                atomicAdd(&g_ks32[bh*HD + col],     acc[nt][rr*2]);
                atomicAdd(&g_ks32[bh*HD + col + 1], acc[nt][rr*2+1]);
            }
        }
    }
}

// ---------------------------------------------------------------------------
// convert kptv/ks -> fp16 B matrix [bh][64][48]; vectorized float4, grid 192.
// ---------------------------------------------------------------------------
__global__ void kvb_conv_kernel()
{
    int i = blockIdx.x * 256 + threadIdx.x;          // 0 .. 64*64*12-1
    if (i >= NBH * 64 * 12) return;
    int bh  = i / 768;
    int rem = i - bh * 768;
    int row = rem / 12;
    int c4  = (rem - row * 12) * 4;

    float4 v;
    if (row < HD)       v = *(const float4*)&g_kptv32[((size_t)bh*HD + row)*HD + c4];
    else if (row == HD) v = *(const float4*)&g_ks32[bh*HD + c4];
    else                v = make_float4(0.f, 0.f, 0.f, 0.f);

    __half2* dst = (__half2*)&g_kvbh[(size_t)bh*64*HD + row*HD + c4];
    dst[0] = __half2(__float2half(v.x), __float2half(v.y));
    dst[1] = __half2(__float2half(v.z), __float2half(v.w));
}

// ---------------------------------------------------------------------------
// attn_out on tensor cores (single fp16): per (bh, 128-token block):
// C[128 x 64] = qp(128x48) @ Bt(64x48)^T ; col 48 = D; att = C[:, :48]/(D+eps)
// ---------------------------------------------------------------------------
#define AO_ROWB 112          // 56 halfs
#define AO_B  14336          // 128*112
#define AO_SMEM 21504        // + 64*112

__global__ __launch_bounds__(256) void attn_out_mma()
{
    extern __shared__ char smem[];
    const uint32_t sb = smem_u32(smem);
    const int tid = threadIdx.x;
    const int wid = tid >> 5;
    const int l   = tid & 31;
    const int bh  = blockIdx.x;
    const int n0  = blockIdx.y * 128;

    // load A (qp): 128 rows x 6 segs = 768 over 256 thr
    #pragma unroll
    for (int i = 0; i < 3; i++) {
        int idx = tid + i * 256;
        int row = idx / 6, seg = idx - row * 6;
        cp16(sb + (uint32_t)(row * AO_ROWB + seg * 16),
             g_qph + ((size_t)bh * Nn + n0 + row) * HD + seg * 8);
    }
    // load B (kvb): 64 rows x 6 segs = 384
    #pragma unroll
    for (int i = 0; i < 2; i++) {
        int idx = tid + i * 256;
        if (idx < 384) {
            int row = idx / 6, seg = idx - row * 6;
            cp16(sb + AO_B + (uint32_t)(row * AO_ROWB + seg * 16),
                 g_kvbh + bh*64*HD + row * HD + seg * 8);
        }
    }
    cp_commit();
    cp_wait<0>();
    __syncthreads();

    float acc[7][4];
    #pragma unroll
    for (int nt = 0; nt < 7; nt++)
        #pragma unroll
        for (int r = 0; r < 4; r++) acc[nt][r] = 0.f;

    // 8 warps x 16 rows = 128
    const uint32_t a_base = (uint32_t)((wid*16 + (l & 15)) * AO_ROWB + (l >> 4) * 16);
    const uint32_t b_base = (uint32_t)((((l >> 4) & 1)*8 + (l & 7)) * AO_ROWB
                                       + ((l >> 3) & 1) * 16);

    #pragma unroll
    for (int k = 0; k < 3; k++) {
        const uint32_t ko = k * 32;
        uint32_t bhf[4][4];
        #pragma unroll
        for (int bt = 0; bt < 4; bt++)
            LDSM4(bhf[bt], sb + AO_B + b_base + bt*16*AO_ROWB + ko);
        uint32_t ah[4];
        LDSM4(ah, sb + a_base + ko);
        #pragma unroll
        for (int nt = 0; nt < 7; nt++)    // nt 6 = D column (48..55)
            mma16816(acc[nt], ah, &bhf[nt >> 1][(nt & 1)*2]);
    }

    // epilogue: D = col 48 (tile 6 col 0, lanes l&3==0); divide, store fp16
    float D0 = __shfl_sync(0xFFFFFFFFu, acc[6][0], l & 0x1C);
    float D1 = __shfl_sync(0xFFFFFFFFu, acc[6][2], l & 0x1C);
    float inv0 = 1.f / (D0 + EPS);
    float inv1 = 1.f / (D1 + EPS);
    int r0 = wid*16 + (l >> 2);
    size_t rowbase0 = ((size_t)bh * Nn + n0 + r0) * HD;
    size_t rowbase1 = ((size_t)bh * Nn + n0 + r0 + 8) * HD;
    #pragma unroll
    for (int nt = 0; nt < 6; nt++) {
        int col = nt*8 + (l & 3)*2;
        __half2 h0 = __half2(__float2half(acc[nt][0]*inv0),
                             __float2half(acc[nt][1]*inv0));
        __half2 h1 = __half2(__float2half(acc[nt][2]*inv1),
                             __float2half(acc[nt][3]*inv1));
        *(__half2*)&g_athi[rowbase0 + col] = h0;
        *(__half2*)&g_athi[rowbase1 + col] = h1;
    }
}

// ---------------------------------------------------------------------------
extern "C" void kernel_launch(void* const* d_in, const int* in_sizes, int n_in,
                              void* d_out, int out_size)
{
    (void)in_sizes; (void)n_in; (void)out_size;
    const float* x     = (const float*)d_in[0];
    const float* Wqkv  = (const float*)d_in[1];
    const float* Wproj = (const float*)d_in[2];
    const float* bproj = (const float*)d_in[3];
    float* out = (float*)d_out;

    // one-time host-side resources (no device memory; identical work per call)
    static cudaStream_t s2 = nullptr;
    static cudaEvent_t evKV = nullptr, evQ = nullptr;
    if (s2 == nullptr) {
        cudaStreamCreateWithFlags(&s2, cudaStreamNonBlocking);
        cudaEventCreateWithFlags(&evKV, cudaEventDisableTiming);
        cudaEventCreateWithFlags(&evQ,  cudaEventDisableTiming);
    }

    cudaFuncSetAttribute(gemm_mma<0>, cudaFuncAttributeMaxDynamicSharedMemorySize, SMEM_TOTAL);
    cudaFuncSetAttribute(gemm_mma<1>, cudaFuncAttributeMaxDynamicSharedMemorySize, SMEM_TOTAL);
    cudaFuncSetAttribute(kv_agg_mma,   cudaFuncAttributeMaxDynamicSharedMemorySize, SMEM2);
    cudaFuncSetAttribute(attn_out_mma, cudaFuncAttributeMaxDynamicSharedMemorySize, AO_SMEM);

    __half *xh, *wq, *wp, *athi;
    cudaGetSymbolAddress((void**)&xh,   g_xh);
    cudaGetSymbolAddress((void**)&wq,   g_wq);
    cudaGetSymbolAddress((void**)&wp,   g_wp);
    cudaGetSymbolAddress((void**)&athi, g_athi);

    prep_kernel<<<(M_ROWS*KDIM/4 + 255)/256, 256>>>(x, Wqkv, Wproj);

    // GEMM1-kv first, alone at full machine (tensor-bound)
    gemm_mma<0><<<dim3(M_ROWS/128, 4), 256, SMEM_TOTAL>>>(
        xh, wq, 2, nullptr, nullptr);                     // y 2-5 (k, v)
    cudaEventRecord(evKV, 0);

    // fork at GEMM1-kv completion:
    //   s2: GEMM1-q (tensor-bound, ~35us)
    //   default: kv_agg + kvb (DRAM-bound, ~20us) -> overlap
    cudaStreamWaitEvent(s2, evKV, 0);
    gemm_mma<0><<<dim3(M_ROWS/128, 2), 256, SMEM_TOTAL, s2>>>(
        xh, wq, 0, nullptr, nullptr);                     // y 0-1 (q)
    cudaEventRecord(evQ, s2);

    kv_agg_mma<<<dim3(NBH, SPLITK), 256, SMEM2>>>();
    kvb_conv_kernel<<<(NBH*64*12 + 255)/256, 256>>>();

    // join: attn_out needs qp (s2) and kvb (default)
    cudaStreamWaitEvent(0, evQ, 0);
    attn_out_mma<<<dim3(NBH, Nn/128), 256, AO_SMEM>>>();

    gemm_mma<1><<<dim3(M_ROWS/128, Cc/192), 256, SMEM_TOTAL>>>(
        athi, wp, 0, bproj, out);
}